// round 11
// baseline (speedup 1.0000x reference)
#include <cuda_runtime.h>
#include <math_constants.h>

// Tiny transformer fully fused into ONE kernel, ONE block of 640 threads.
// CONTEXT=5, DIM=32, HEADS=4 (hd=8), NTOK=13, LAYERS=4.
//
// 4 warp-aligned groups of 160 threads:
//   A (0..159):   Q matmul; scores+softmax; Yps via per-head Vph.  regs: Wq
//   B (160..319): K matmul; final unembed.                        regs: Wk->Wu
//   C (320..479): H=relu(.@W1), Y=.@W2, X residual.               regs: W1+W2
//   D (480..639): V matmul; Vph[h][k][d] = sum_{j in head h} V[k,j]Wp[j,d]
//                 (off the critical path).                        regs: Wv+Wp
//
// EXACT per-head factorization (S is block-diagonal per head):
//   Yproj[q,d] = bp[d] + sum_h sum_k S[h,q,k] * Vph[h][k][d]
// D computes Vph concurrently with A's score/softmax chain; A gathers the 4
// heads' normalized weights via __shfl (each 8-lane subgroup holds its own
// head's weights redundantly), replacing the Ycat bounce + Wp matmul.
//
// Producer-arrive / consumer-sync named barriers (prefetch AFTER arrive):
//   bar1 (320): B arrives after K;    A syncs before scores.
//   bar3 (320): D arrives after Vph;  A syncs before the accumulation.
//   bar2 (320): A arrives after Yps;  C syncs.
//   bar0 (640): C arrives after the X update; A,B,D sync at loop top.
//               (prologue instance: A,C arrive; B,D sync -> X(0) ready)
// Softmax: tiny scores -> max-subtraction unnecessary.
// tokemb staged to smem so the tok->embedding gather is one parallel trip.

#define CTX    5
#define DIM    32
#define NTOK   13
#define HEADS  4
#define HD     8
#define LAYERS 4
#define SCALE  0.17677669529663687f   // 1/sqrt(32)
#define FULL   0xFFFFFFFFu

#define BAR_SYNC(id, n)   asm volatile("bar.sync %0, %1;"   :: "n"(id), "n"(n) : "memory")
#define BAR_ARRIVE(id, n) asm volatile("bar.arrive %0, %1;" :: "n"(id), "n"(n) : "memory")

__global__ __launch_bounds__(640, 1)
void transformer_fused_kernel(
    const int*   __restrict__ toks,
    const float* __restrict__ pos,
    const float* __restrict__ tokemb,
    const float* __restrict__ gWq,
    const float* __restrict__ gWk,
    const float* __restrict__ gWv,
    const float* __restrict__ gWp,
    const float* __restrict__ gbp,
    const float* __restrict__ gW1,
    const float* __restrict__ gb1,
    const float* __restrict__ gW2,
    const float* __restrict__ gb2,
    const float* __restrict__ gWu,
    const float* __restrict__ gbu,
    float*       __restrict__ out)
{
    __shared__ __align__(16) float Xs  [CTX * DIM];
    __shared__ __align__(16) float Qs  [CTX * DIM];
    __shared__ __align__(16) float Ks  [CTX * DIM];
    __shared__ __align__(16) float Vt  [CTX * DIM];        // V bounce (D)
    __shared__ __align__(16) float Vph [HEADS * CTX * DIM];// per-head V@Wp
    __shared__ __align__(16) float Yps [CTX * DIM];
    __shared__ __align__(16) float Hs  [CTX * DIM];        // H bounce (C)
    __shared__ __align__(16) float temb[NTOK * DIM];
    __shared__ int toks_s[CTX];

    const int tid = threadIdx.x;
    const int g   = tid / 160;        // 0=A, 1=B, 2=C, 3=D (warp-aligned)
    const int r   = tid - g * 160;    // 0..159
    const int c   = r >> 5;           // context row (warp-uniform)
    const int d   = r & 31;           // feature column (lane)

    float w0[DIM];    // A: Wq   B: Wk        C: W1   D: Wv
    float w1r[DIM];   //         B: Wu(end)   C: W2   D: Wp
    float b0 = 0.f;   // A: bp   B: bu(end)   C: b1
    float b1v = 0.f;  //                      C: b2

    // ---- Prologue: stage toks/temb, prefetch layer-0 weights (parallel) ----
    if (tid < CTX) toks_s[tid] = toks[tid];
    float posv = 0.f;
    if (g == 0) {
        posv = pos[r];
        #pragma unroll
        for (int i = 0; i < DIM; ++i) w0[i] = gWq[i * DIM + d];
        b0 = gbp[d];
    } else if (g == 1) {
        #pragma unroll
        for (int i = 0; i < DIM; ++i) w0[i] = gWk[i * DIM + d];
    } else if (g == 2) {
        if (r < (NTOK * DIM / 4))     // 104 float4: whole embedding table
            ((float4*)temb)[r] = ((const float4*)tokemb)[r];
        #pragma unroll
        for (int i = 0; i < DIM; ++i) {
            w0[i]  = gW1[i * DIM + d];
            w1r[i] = gW2[i * DIM + d];
        }
        b0  = gb1[d];
        b1v = gb2[d];
    } else {
        #pragma unroll
        for (int i = 0; i < DIM; ++i) {
            w0[i]  = gWv[i * DIM + d];
            w1r[i] = gWp[i * DIM + d];
        }
    }
    __syncthreads();                  // toks_s + temb visible

    // ---- Embedding (A); prologue bar0: A,C arrive; B,D sync at loop top ----
    if (g == 0) {
        Xs[r] = temb[toks_s[c] * DIM + d] + posv;
        __syncwarp();                 // warp c produced row c
        BAR_ARRIVE(0, 640);
    } else if (g == 2) {
        BAR_ARRIVE(0, 640);
    }

    #pragma unroll 1
    for (int l = 0; l < LAYERS; ++l) {
        const int ln = l + 1;

        if (g == 0) {
            // ===== Phase 1 (A): Q = X @ Wq -> Qs =====
            if (l > 0) BAR_SYNC(0, 640);           // wait for X(l)
            {
                const float4* xr = (const float4*)(Xs + c * DIM);
                float a0 = 0.f, a1 = 0.f, a2 = 0.f, a3 = 0.f;
                #pragma unroll
                for (int i = 0; i < 8; ++i) {
                    const float4 x = xr[i];
                    a0 = fmaf(x.x, w0[4 * i    ], a0);
                    a1 = fmaf(x.y, w0[4 * i + 1], a1);
                    a2 = fmaf(x.z, w0[4 * i + 2], a2);
                    a3 = fmaf(x.w, w0[4 * i + 3], a3);
                }
                Qs[r] = (a0 + a1) + (a2 + a3);
                __syncwarp();
            }
            if (l < LAYERS - 1) {                  // hidden in wait-for-K slack
                #pragma unroll
                for (int i = 0; i < DIM; ++i)
                    w0[i] = gWq[ln * DIM * DIM + i * DIM + d];
            }
            BAR_SYNC(1, 320);                      // K ready

            // ===== Phase 2 (A): per-head softmax, then cross-head sum =====
            {
                const int h    = d >> 3;
                const int base = h * HD;
                const float4 qa = *(const float4*)(Qs + c * DIM + base);
                const float4 qb = *(const float4*)(Qs + c * DIM + base + 4);
                float e[CTX];
                #pragma unroll
                for (int k = 0; k < CTX; ++k) {
                    if (k <= c) {
                        const float4 ka = *(const float4*)(Ks + k * DIM + base);
                        const float4 kb = *(const float4*)(Ks + k * DIM + base + 4);
                        float s0 = qa.x * ka.x + qa.z * ka.z;
                        float s1 = qa.y * ka.y + qa.w * ka.w;
                        s0 += qb.x * kb.x + qb.z * kb.z;
                        s1 += qb.y * kb.y + qb.w * kb.w;
                        e[k] = __expf((s0 + s1) * SCALE);
                    } else {
                        e[k] = 0.f;
                    }
                }
                const float inv =
                    __fdividef(1.f, (e[0] + e[1]) + (e[2] + e[3]) + e[4]);
                float et[CTX];
                #pragma unroll
                for (int k = 0; k < CTX; ++k) et[k] = e[k] * inv;

                BAR_SYNC(3, 320);                  // Vph ready (usually already)
                // Yps[c,d] = bp[d] + sum_h sum_k S[h,c,k] * Vph[h][k][d].
                // Lanes h*8 hold head-h's et[] (redundant across the 8-lane
                // subgroup) -> gather via shfl.
                float y0 = b0, y1 = 0.f, y2 = 0.f, y3 = 0.f;
                #pragma unroll
                for (int k = 0; k < CTX; ++k) {
                    const float s0 = __shfl_sync(FULL, et[k], 0);
                    const float s1 = __shfl_sync(FULL, et[k], 8);
                    const float s2 = __shfl_sync(FULL, et[k], 16);
                    const float s3 = __shfl_sync(FULL, et[k], 24);
                    y0 = fmaf(s0, Vph[0 * CTX * DIM + k * DIM + d], y0);
                    y1 = fmaf(s1, Vph[1 * CTX * DIM + k * DIM + d], y1);
                    y2 = fmaf(s2, Vph[2 * CTX * DIM + k * DIM + d], y2);
                    y3 = fmaf(s3, Vph[3 * CTX * DIM + k * DIM + d], y3);
                }
                Yps[r] = (y0 + y1) + (y2 + y3);
            }
            BAR_ARRIVE(2, 320);                    // release C immediately
            if (l < LAYERS - 1)                    // prefetch OFF critical path
                b0 = gbp[ln * DIM + d];
        } else if (g == 1) {
            // ===== Phase 1 (B): K = X @ Wk -> Ks (short leg, early bar1) =====
            BAR_SYNC(0, 640);                      // wait for X(l)
            {
                const float4* xr = (const float4*)(Xs + c * DIM);
                float k0 = 0.f, k1 = 0.f, k2 = 0.f, k3 = 0.f;
                #pragma unroll
                for (int i = 0; i < 8; ++i) {
                    const float4 x = xr[i];
                    k0 = fmaf(x.x, w0[4 * i    ], k0);
                    k1 = fmaf(x.y, w0[4 * i + 1], k1);
                    k2 = fmaf(x.z, w0[4 * i + 2], k2);
                    k3 = fmaf(x.w, w0[4 * i + 3], k3);
                }
                Ks[r] = (k0 + k1) + (k2 + k3);
            }
            BAR_ARRIVE(1, 320);                    // release A immediately
            if (l < LAYERS - 1) {                  // prefetch OFF critical path
                #pragma unroll
                for (int i = 0; i < DIM; ++i)
                    w0[i] = gWk[ln * DIM * DIM + i * DIM + d];
            } else if (r < CTX * NTOK) {           // last layer: Wu + bu
                const int t = r % NTOK;
                #pragma unroll
                for (int i = 0; i < DIM; ++i)
                    w1r[i] = gWu[i * NTOK + t];
                b0 = gbu[t];
            }
        } else if (g == 3) {
            // ===== Phase 1b (D): V = X @ Wv ; per-head Vph = V_h @ Wp =====
            BAR_SYNC(0, 640);                      // wait for X(l)
            {
                const float4* xr = (const float4*)(Xs + c * DIM);
                float v0 = 0.f, v1 = 0.f, v2 = 0.f, v3 = 0.f;
                #pragma unroll
                for (int i = 0; i < 8; ++i) {
                    const float4 x = xr[i];
                    v0 = fmaf(x.x, w0[4 * i    ], v0);
                    v1 = fmaf(x.y, w0[4 * i + 1], v1);
                    v2 = fmaf(x.z, w0[4 * i + 2], v2);
                    v3 = fmaf(x.w, w0[4 * i + 3], v3);
                }
                Vt[r] = (v0 + v1) + (v2 + v3);     // intra-warp bounce
                __syncwarp();
                // Vph[h][c][d] = sum_{j=0..7} V[c][h*8+j] * Wp[h*8+j][d]
                float p0 = 0.f, p1 = 0.f, p2 = 0.f, p3 = 0.f;
                #pragma unroll
                for (int j = 0; j < HD; ++j) {
                    p0 = fmaf(Vt[c * DIM +      j], w1r[     j], p0);
                    p1 = fmaf(Vt[c * DIM +  8 + j], w1r[ 8 + j], p1);
                    p2 = fmaf(Vt[c * DIM + 16 + j], w1r[16 + j], p2);
                    p3 = fmaf(Vt[c * DIM + 24 + j], w1r[24 + j], p3);
                }
                Vph[0 * CTX * DIM + c * DIM + d] = p0;
                Vph[1 * CTX * DIM + c * DIM + d] = p1;
                Vph[2 * CTX * DIM + c * DIM + d] = p2;
                Vph[3 * CTX * DIM + c * DIM + d] = p3;
            }
            BAR_ARRIVE(3, 320);                    // release A's accumulation
            if (l < LAYERS - 1) {                  // prefetch OFF critical path
                #pragma unroll
                for (int i = 0; i < DIM; ++i) {
                    w0[i]  = gWv[ln * DIM * DIM + i * DIM + d];
                    w1r[i] = gWp[ln * DIM * DIM + i * DIM + d];
                }
            }
        } else {
            // ===== Phase 3 (C): H=relu(Yp@W1+b1); Y=H@W2+b2; X update =====
            BAR_SYNC(2, 320);                      // wait for Yps
            {
                const float4* xr = (const float4*)(Yps + c * DIM);
                float a0 = b0, a1 = 0.f, a2 = 0.f, a3 = 0.f;
                #pragma unroll
                for (int i = 0; i < 8; ++i) {
                    const float4 x = xr[i];
                    a0 = fmaf(x.x, w0[4 * i    ], a0);
                    a1 = fmaf(x.y, w0[4 * i + 1], a1);
                    a2 = fmaf(x.z, w0[4 * i + 2], a2);
                    a3 = fmaf(x.w, w0[4 * i + 3], a3);
                }
                const float hval = fmaxf((a0 + a1) + (a2 + a3), 0.f);

                Hs[r] = hval;                      // intra-warp bounce
                __syncwarp();
                const float4* hr = (const float4*)(Hs + c * DIM);
                float y0 = b1v, y1 = 0.f, y2 = 0.f, y3 = 0.f;
                #pragma unroll
                for (int i = 0; i < 8; ++i) {
                    const float4 x = hr[i];
                    y0 = fmaf(x.x, w1r[4 * i    ], y0);
                    y1 = fmaf(x.y, w1r[4 * i + 1], y1);
                    y2 = fmaf(x.z, w1r[4 * i + 2], y2);
                    y3 = fmaf(x.w, w1r[4 * i + 3], y3);
                }
                // sole reader+writer of Xs[r] here: no hazard
                Xs[r] += ((y0 + y1) + (y2 + y3)) + Yps[r];
            }
            BAR_ARRIVE(0, 640);                    // release A,B,D immediately
            if (l < LAYERS - 1) {                  // prefetch OFF critical path
                #pragma unroll
                for (int i = 0; i < DIM; ++i) {
                    w0[i]  = gW1[ln * DIM * DIM + i * DIM + d];
                    w1r[i] = gW2[ln * DIM * DIM + i * DIM + d];
                }
                b0  = gb1[ln * DIM + d];
                b1v = gb2[ln * DIM + d];
            }
        }
    }

    // ---- Final X barrier, then epilogue (B, Wu in regs) ----
    if (g == 0 || g == 1 || g == 3) {
        BAR_SYNC(0, 640);
        if (g == 1 && r < CTX * NTOK) {
            const int cc = r / NTOK;
            const float4* xr = (const float4*)(Xs + cc * DIM);
            float y0 = b0, y1 = 0.f, y2 = 0.f, y3 = 0.f;
            #pragma unroll
            for (int i = 0; i < 8; ++i) {
                const float4 x = xr[i];
                y0 = fmaf(x.x, w1r[4 * i    ], y0);
                y1 = fmaf(x.y, w1r[4 * i + 1], y1);
                y2 = fmaf(x.z, w1r[4 * i + 2], y2);
                y3 = fmaf(x.w, w1r[4 * i + 3], y3);
            }
            out[r] = (y0 + y1) + (y2 + y3);
        }
    }
}

extern "C" void kernel_launch(void* const* d_in, const int* in_sizes, int n_in,
                              void* d_out, int out_size) {
    (void)in_sizes; (void)n_in; (void)out_size;
    const int*   toks   = (const int*)  d_in[0];
    const float* pos    = (const float*)d_in[1];
    const float* tokemb = (const float*)d_in[2];
    const float* Wq     = (const float*)d_in[3];
    const float* Wk     = (const float*)d_in[4];
    const float* Wv     = (const float*)d_in[5];
    const float* Wp     = (const float*)d_in[6];
    const float* bp     = (const float*)d_in[7];
    const float* W1     = (const float*)d_in[8];
    const float* b1     = (const float*)d_in[9];
    const float* W2     = (const float*)d_in[10];
    const float* b2     = (const float*)d_in[11];
    const float* Wu     = (const float*)d_in[12];
    const float* bu     = (const float*)d_in[13];
    float* out = (float*)d_out;

    transformer_fused_kernel<<<1, 640>>>(toks, pos, tokemb, Wq, Wk, Wv, Wp, bp,
                                         W1, b1, W2, b2, Wu, bu, out);
}

// round 12
// speedup vs baseline: 1.1192x; 1.1192x over previous
#include <cuda_runtime.h>
#include <math_constants.h>

// Tiny transformer fully fused into ONE kernel, ONE block of 480 threads.
// CONTEXT=5, DIM=32, HEADS=4 (hd=8), NTOK=13, LAYERS=4.
//
// R8 skeleton (best known): 3 warp-aligned groups of 160 threads:
//   A (0..159):   Q matmul; scores+softmax+Ycat+Yproj.  regs: Wq + Wp
//   B (160..319): K,V matmuls; final unembed.           regs: Wk + Wv->Wu
//   C (320..479): H=relu(.@W1), Y=.@W2, X residual.     regs: W1 + W2
// Producer-arrive / consumer-sync named barriers; weight prefetch AFTER the
// arrive (off the critical path). tokemb staged to smem at entry.
//
// NEW in R12: the kernel is FMA-ISSUE-bound (FFMA rt=2 cyc/warp-instr per
// SMSP). All 32-deep dot products use packed fma.rn.f32x2 (SASS FFMA2):
// 16 packed FMAs instead of 32 scalar ones. Weights are packed into u64
// pairs at prefetch; activations are read as ulonglong2 (LDS.128), so the
// packed operands need no extra movs on the critical path.

#define CTX    5
#define DIM    32
#define NTOK   13
#define HEADS  4
#define HD     8
#define LAYERS 4
#define SCALE  0.17677669529663687f   // 1/sqrt(32)
#define FULL   0xFFFFFFFFu

typedef unsigned long long u64;

#define BAR_SYNC(id, n)   asm volatile("bar.sync %0, %1;"   :: "n"(id), "n"(n) : "memory")
#define BAR_ARRIVE(id, n) asm volatile("bar.arrive %0, %1;" :: "n"(id), "n"(n) : "memory")

#define FFMA2(acc, a, b) asm("fma.rn.f32x2 %0, %1, %2, %0;" : "+l"(acc) : "l"(a), "l"(b))
#define FMUL2(d, a, b)   asm("mul.rn.f32x2 %0, %1, %2;" : "=l"(d) : "l"(a), "l"(b))
#define FADD2(d, a, b)   asm("add.rn.f32x2 %0, %1, %2;" : "=l"(d) : "l"(a), "l"(b))
#define PACK2(p, lo, hi) asm("mov.b64 %0, {%1, %2};" : "=l"(p) : "f"(lo), "f"(hi))
#define UNPK2(lo, hi, p) asm("mov.b64 {%0, %1}, %2;" : "=f"(lo), "=f"(hi) : "l"(p))

// Load a 32-float smem row (16B-aligned) as 16 packed f32x2 operands.
#define LOADX16(xv, ptr) do {                                          \
    const ulonglong2* _p = (const ulonglong2*)(ptr);                   \
    _Pragma("unroll")                                                  \
    for (int _i = 0; _i < 8; ++_i) {                                   \
        ulonglong2 _t = _p[_i];                                        \
        (xv)[2 * _i] = _t.x; (xv)[2 * _i + 1] = _t.y;                  \
    } } while (0)

// 32-element dot via 16 packed FMAs, 4 packed accumulators (depth 4).
__device__ __forceinline__ float dot32p(const u64* xv, const u64* wp, float bias) {
    u64 a0, a1, a2, a3;
    PACK2(a0, bias, 0.0f);
    a1 = 0ull; a2 = 0ull; a3 = 0ull;   // (0.f, 0.f) bit pattern
    #pragma unroll
    for (int i = 0; i < 4; ++i) {
        FFMA2(a0, xv[4 * i    ], wp[4 * i    ]);
        FFMA2(a1, xv[4 * i + 1], wp[4 * i + 1]);
        FFMA2(a2, xv[4 * i + 2], wp[4 * i + 2]);
        FFMA2(a3, xv[4 * i + 3], wp[4 * i + 3]);
    }
    u64 s0, s1;
    FADD2(s0, a0, a1);
    FADD2(s1, a2, a3);
    FADD2(s0, s0, s1);
    float lo, hi; UNPK2(lo, hi, s0);
    return lo + hi;
}

// Pack one weight column (lane d) of a [DIM,DIM] matrix into 16 u64 pairs.
#define PREFETCH_W(wp, gW, off, d) do {                                \
    _Pragma("unroll")                                                  \
    for (int _j = 0; _j < 16; ++_j) {                                  \
        const float _lo = (gW)[(off) + (2 * _j)     * DIM + (d)];      \
        const float _hi = (gW)[(off) + (2 * _j + 1) * DIM + (d)];      \
        PACK2((wp)[_j], _lo, _hi);                                     \
    } } while (0)

__global__ __launch_bounds__(480, 1)
void transformer_fused_kernel(
    const int*   __restrict__ toks,
    const float* __restrict__ pos,
    const float* __restrict__ tokemb,
    const float* __restrict__ gWq,
    const float* __restrict__ gWk,
    const float* __restrict__ gWv,
    const float* __restrict__ gWp,
    const float* __restrict__ gbp,
    const float* __restrict__ gW1,
    const float* __restrict__ gb1,
    const float* __restrict__ gW2,
    const float* __restrict__ gb2,
    const float* __restrict__ gWu,
    const float* __restrict__ gbu,
    float*       __restrict__ out)
{
    __shared__ __align__(16) float Xs  [CTX * DIM];
    __shared__ __align__(16) float Qs  [CTX * DIM];   // Q, then Ycat bounce
    __shared__ __align__(16) float Ks  [CTX * DIM];
    __shared__ __align__(16) float Vs  [CTX * DIM];
    __shared__ __align__(16) float Yps [CTX * DIM];
    __shared__ __align__(16) float Hs  [CTX * DIM];   // H bounce (group C)
    __shared__ __align__(16) float temb[NTOK * DIM];
    __shared__ int toks_s[CTX];

    const int tid = threadIdx.x;
    const int g   = tid / 160;        // 0=A, 1=B, 2=C (warp-aligned)
    const int r   = tid - g * 160;    // 0..159
    const int c   = r >> 5;           // context row (warp-uniform)
    const int d   = r & 31;           // feature column (lane)

    u64 w0p[16];      // A: Wq   B: Wk        C: W1   (packed columns)
    u64 w1p[16];      // A: Wp   B: Wv -> Wu  C: W2
    float b0 = 0.f;   // A: bp   B: bu(end)   C: b1
    float b1v = 0.f;  //                      C: b2

    // ---- Prologue: stage toks/temb, prefetch layer-0 weights (parallel) ----
    if (tid < CTX) toks_s[tid] = toks[tid];
    float posv = 0.f;
    if (g == 0) {
        posv = pos[r];
        PREFETCH_W(w0p, gWq, 0, d);
        PREFETCH_W(w1p, gWp, 0, d);
        b0 = gbp[d];
    } else if (g == 1) {
        PREFETCH_W(w0p, gWk, 0, d);
        PREFETCH_W(w1p, gWv, 0, d);
    } else {
        if (r < (NTOK * DIM / 4))     // 104 float4: whole embedding table
            ((float4*)temb)[r] = ((const float4*)tokemb)[r];
        PREFETCH_W(w0p, gW1, 0, d);
        PREFETCH_W(w1p, gW2, 0, d);
        b0  = gb1[d];
        b1v = gb2[d];
    }
    __syncthreads();                  // toks_s + temb visible

    // ---- Embedding (A); prologue bar0: A,C arrive; B syncs at loop top ----
    if (g == 0) {
        Xs[r] = temb[toks_s[c] * DIM + d] + posv;
        __syncwarp();                 // warp c produced row c
        BAR_ARRIVE(0, 480);
    } else if (g == 2) {
        BAR_ARRIVE(0, 480);
    }

    #pragma unroll 1
    for (int l = 0; l < LAYERS; ++l) {
        const int ln = l + 1;
        const int off = ln * DIM * DIM;

        if (g == 0) {
            // ===== Phase 1 (A): Q = X @ Wq -> Qs =====
            if (l > 0) BAR_SYNC(0, 480);           // wait for X(l)
            {
                u64 xv[16];
                LOADX16(xv, Xs + c * DIM);
                Qs[r] = dot32p(xv, w0p, 0.f);
                __syncwarp();
            }
            if (l < LAYERS - 1)                    // hidden in wait-for-B slack
                PREFETCH_W(w0p, gWq, off, d);
            BAR_SYNC(1, 320);                      // wait for K,V

            // ===== Phase 2 (A): attention inline + Yproj (smem bounce) =====
            {
                const int base = (d >> 3) * HD;
                u64 qv[4];
                {
                    const ulonglong2* qp = (const ulonglong2*)(Qs + c * DIM + base);
                    const ulonglong2 q0 = qp[0], q1 = qp[1];
                    qv[0] = q0.x; qv[1] = q0.y; qv[2] = q1.x; qv[3] = q1.y;
                }
                float e[CTX];
                #pragma unroll
                for (int k = 0; k < CTX; ++k) {
                    if (k <= c) {
                        const ulonglong2* kp = (const ulonglong2*)(Ks + k * DIM + base);
                        const ulonglong2 k0 = kp[0], k1 = kp[1];
                        u64 acc;
                        FMUL2(acc, qv[0], k0.x);
                        FFMA2(acc, qv[1], k0.y);
                        FFMA2(acc, qv[2], k1.x);
                        FFMA2(acc, qv[3], k1.y);
                        float lo, hi; UNPK2(lo, hi, acc);
                        e[k] = __expf((lo + hi) * SCALE);
                    } else {
                        e[k] = 0.f;
                    }
                }
                const float inv =
                    __fdividef(1.f, (e[0] + e[1]) + (e[2] + e[3]) + e[4]);
                float y = e[0] * Vs[0 * DIM + d];
                y = fmaf(e[1], Vs[1 * DIM + d], y);
                y = fmaf(e[2], Vs[2 * DIM + d], y);
                y = fmaf(e[3], Vs[3 * DIM + d], y);
                y = fmaf(e[4], Vs[4 * DIM + d], y);
                y *= inv;                               // Ycat[c][d]

                // intra-warp bounce: row c lives in warp c
                Qs[r] = y;
                __syncwarp();
                u64 xv[16];
                LOADX16(xv, Qs + c * DIM);
                Yps[r] = dot32p(xv, w1p, b0);           // Ycat @ Wp + bp
            }
            BAR_ARRIVE(2, 320);                    // release C immediately
            if (l < LAYERS - 1) {                  // prefetch OFF critical path
                PREFETCH_W(w1p, gWp, off, d);
                b0 = gbp[ln * DIM + d];
            }
        } else if (g == 1) {
            // ===== Phase 1 (B): K,V = X @ {Wk,Wv} -> Ks,Vs =====
            BAR_SYNC(0, 480);                      // wait for X(l)
            {
                u64 xv[16];
                LOADX16(xv, Xs + c * DIM);
                Ks[r] = dot32p(xv, w0p, 0.f);
                Vs[r] = dot32p(xv, w1p, 0.f);
            }
            BAR_ARRIVE(1, 320);                    // release A immediately
            if (l < LAYERS - 1) {                  // prefetch OFF critical path
                PREFETCH_W(w0p, gWk, off, d);
                PREFETCH_W(w1p, gWv, off, d);
            } else if (r < CTX * NTOK) {           // last layer: Wu + bu
                const int t = r % NTOK;
                #pragma unroll
                for (int j = 0; j < 16; ++j) {
                    const float lo = gWu[(2 * j)     * NTOK + t];
                    const float hi = gWu[(2 * j + 1) * NTOK + t];
                    PACK2(w1p[j], lo, hi);
                }
                b0 = gbu[t];
            }
        } else {
            // ===== Phase 3 (C): H=relu(Yp@W1+b1); Y=H@W2+b2; X update =====
            BAR_SYNC(2, 320);                      // wait for Yps
            {
                u64 xv[16];
                LOADX16(xv, Yps + c * DIM);
                const float hval = fmaxf(dot32p(xv, w0p, b0), 0.f);

                Hs[r] = hval;                      // intra-warp bounce
                __syncwarp();
                u64 hv[16];
                LOADX16(hv, Hs + c * DIM);
                const float y = dot32p(hv, w1p, b1v);
                // sole reader+writer of Xs[r] here: no hazard
                Xs[r] += y + Yps[r];
            }
            BAR_ARRIVE(0, 480);                    // release A,B immediately
            if (l < LAYERS - 1) {                  // prefetch OFF critical path
                PREFETCH_W(w0p, gW1, off, d);
                PREFETCH_W(w1p, gW2, off, d);
                b0  = gb1[ln * DIM + d];
                b1v = gb2[ln * DIM + d];
            }
        }
    }

    // ---- Final X barrier, then epilogue (B, Wu in regs) ----
    if (g < 2) {
        BAR_SYNC(0, 480);
        if (g == 1 && r < CTX * NTOK) {
            const int cc = r / NTOK;
            u64 xv[16];
            LOADX16(xv, Xs + cc * DIM);
            out[r] = dot32p(xv, w1p, b0);
        }
    }
}

extern "C" void kernel_launch(void* const* d_in, const int* in_sizes, int n_in,
                              void* d_out, int out_size) {
    (void)in_sizes; (void)n_in; (void)out_size;
    const int*   toks   = (const int*)  d_in[0];
    const float* pos    = (const float*)d_in[1];
    const float* tokemb = (const float*)d_in[2];
    const float* Wq     = (const float*)d_in[3];
    const float* Wk     = (const float*)d_in[4];
    const float* Wv     = (const float*)d_in[5];
    const float* Wp     = (const float*)d_in[6];
    const float* bp     = (const float*)d_in[7];
    const float* W1     = (const float*)d_in[8];
    const float* b1     = (const float*)d_in[9];
    const float* W2     = (const float*)d_in[10];
    const float* b2     = (const float*)d_in[11];
    const float* Wu     = (const float*)d_in[12];
    const float* bu     = (const float*)d_in[13];
    float* out = (float*)d_out;

    transformer_fused_kernel<<<1, 480>>>(toks, pos, tokemb, Wq, Wk, Wv, Wp, bp,
                                         W1, b1, W2, b2, Wu, bu, out);
}

// round 14
// speedup vs baseline: 1.1527x; 1.0299x over previous
#include <cuda_runtime.h>
#include <math_constants.h>

// Tiny transformer fully fused into ONE kernel, ONE block of 320 threads.
// CONTEXT=5, DIM=32, HEADS=4 (hd=8), NTOK=13, LAYERS=4.
//
// TWO warp-aligned groups of 160 threads:
//   A (0..159):   owns the whole row pipeline: Q -> attention -> Yproj ->
//                 MLP -> residual. regs: packed Wq+Wp+W1+W2 (128 regs).
//   B (160..319): K,V matmuls; final unembed. regs: packed Wk+Wv -> Wu.
// 320 threads => up to ~204 regs/thread, so A CAN hold 4 packed matrices.
//
// Critical path crosses only ONE barrier per layer (bar1: K,V ready).
//   bar1 (320): B arrives after K,V; A syncs before scores.
//   bar0 (320): A arrives after the X update (never waits); B syncs at
//               loop top. Prologue instance: A arrives after embedding.
// All row-wise chained matmuls use intra-warp smem bounces (STS; __syncwarp;
// LDS.128) — warp c owns row c. All 32-deep dots are packed fma.rn.f32x2
// (16 FFMA2 instead of 32 FFMA). Weight prefetch for layer l+1 is issued
// right after each matrix's last use, filling A's dep-stall gaps.
// Softmax: tiny scores -> max-subtraction unnecessary.
// tokemb staged to smem (by B) so the tok->embedding gather is parallel.

#define CTX    5
#define DIM    32
#define NTOK   13
#define HEADS  4
#define HD     8
#define LAYERS 4
#define SCALE  0.17677669529663687f   // 1/sqrt(32)
#define FULL   0xFFFFFFFFu

typedef unsigned long long u64;

#define BAR_SYNC(id, n)   asm volatile("bar.sync %0, %1;"   :: "n"(id), "n"(n) : "memory")
#define BAR_ARRIVE(id, n) asm volatile("bar.arrive %0, %1;" :: "n"(id), "n"(n) : "memory")

#define FFMA2(acc, a, b) asm("fma.rn.f32x2 %0, %1, %2, %0;" : "+l"(acc) : "l"(a), "l"(b))
#define FMUL2(d, a, b)   asm("mul.rn.f32x2 %0, %1, %2;" : "=l"(d) : "l"(a), "l"(b))
#define FADD2(d, a, b)   asm("add.rn.f32x2 %0, %1, %2;" : "=l"(d) : "l"(a), "l"(b))
#define PACK2(p, lo, hi) asm("mov.b64 %0, {%1, %2};" : "=l"(p) : "f"(lo), "f"(hi))
#define UNPK2(lo, hi, p) asm("mov.b64 {%0, %1}, %2;" : "=f"(lo), "=f"(hi) : "l"(p))

// 32-elem dot: loads folded in (few live temps), 16 packed FMAs, depth-4.
__device__ __forceinline__ float dot32s(const float* row, const u64* wp, float bias) {
    const ulonglong2* p = (const ulonglong2*)row;
    u64 a0, a1, a2, a3;
    PACK2(a0, bias, 0.0f);
    a1 = 0ull; a2 = 0ull; a3 = 0ull;
    #pragma unroll
    for (int i = 0; i < 4; ++i) {
        const ulonglong2 t0 = p[2 * i];
        const ulonglong2 t1 = p[2 * i + 1];
        FFMA2(a0, t0.x, wp[4 * i    ]);
        FFMA2(a1, t0.y, wp[4 * i + 1]);
        FFMA2(a2, t1.x, wp[4 * i + 2]);
        FFMA2(a3, t1.y, wp[4 * i + 3]);
    }
    u64 s0, s1;
    FADD2(s0, a0, a1);
    FADD2(s1, a2, a3);
    FADD2(s0, s0, s1);
    float lo, hi; UNPK2(lo, hi, s0);
    return lo + hi;
}

// Pack one weight column (lane d) of a [DIM,DIM] matrix into 16 u64 pairs.
#define PREFETCH_W(wp, gW, off, d) do {                                \
    _Pragma("unroll")                                                  \
    for (int _j = 0; _j < 16; ++_j) {                                  \
        const float _lo = (gW)[(off) + (2 * _j)     * DIM + (d)];      \
        const float _hi = (gW)[(off) + (2 * _j + 1) * DIM + (d)];      \
        PACK2((wp)[_j], _lo, _hi);                                     \
    } } while (0)

__global__ __launch_bounds__(320, 1)
void transformer_fused_kernel(
    const int*   __restrict__ toks,
    const float* __restrict__ pos,
    const float* __restrict__ tokemb,
    const float* __restrict__ gWq,
    const float* __restrict__ gWk,
    const float* __restrict__ gWv,
    const float* __restrict__ gWp,
    const float* __restrict__ gbp,
    const float* __restrict__ gW1,
    const float* __restrict__ gb1,
    const float* __restrict__ gW2,
    const float* __restrict__ gb2,
    const float* __restrict__ gWu,
    const float* __restrict__ gbu,
    float*       __restrict__ out)
{
    __shared__ __align__(16) float Xs  [CTX * DIM];
    __shared__ __align__(16) float Qs  [CTX * DIM];   // Q, then Ycat bounce
    __shared__ __align__(16) float Ks  [CTX * DIM];
    __shared__ __align__(16) float Vs  [CTX * DIM];
    __shared__ __align__(16) float Yps [CTX * DIM];   // Yproj bounce
    __shared__ __align__(16) float Hs  [CTX * DIM];   // H bounce
    __shared__ __align__(16) float temb[NTOK * DIM];
    __shared__ int toks_s[CTX];

    const int tid = threadIdx.x;
    const int g   = tid / 160;        // 0=A, 1=B (warp-aligned)
    const int r   = tid - g * 160;    // 0..159
    const int c   = r >> 5;           // context row (warp-uniform)
    const int d   = r & 31;           // feature column (lane)

    // A: wq,wp,w1,w2 packed; B: wk,wv (wv -> Wu at the end); others unused.
    u64 wqp[16], wpp[16];             // A: Wq, Wp       B: Wk, Wv->Wu
    u64 w1p[16], w2p[16];             // A: W1, W2       B: unused
    float bpv = 0.f, b1v = 0.f, b2v = 0.f;   // A biases; B: bpv = bu(end)

    // ---- Prologue: stage toks/temb, prefetch layer-0 weights (parallel) ----
    if (tid < CTX) toks_s[tid] = toks[tid];
    float posv = 0.f;
    if (g == 0) {
        posv = pos[r];
        PREFETCH_W(wqp, gWq, 0, d);
        PREFETCH_W(wpp, gWp, 0, d);
        PREFETCH_W(w1p, gW1, 0, d);
        PREFETCH_W(w2p, gW2, 0, d);
        bpv = gbp[d];
        b1v = gb1[d];
        b2v = gb2[d];
    } else {
        if (r < (NTOK * DIM / 4))     // 104 float4: whole embedding table
            ((float4*)temb)[r] = ((const float4*)tokemb)[r];
        PREFETCH_W(wqp, gWk, 0, d);   // B: wqp = Wk, wpp = Wv
        PREFETCH_W(wpp, gWv, 0, d);
    }
    __syncthreads();                  // toks_s + temb visible

    // ---- Embedding (A); prologue bar0 arrive: B syncs at loop top ----
    if (g == 0) {
        Xs[r] = temb[toks_s[c] * DIM + d] + posv;
        __syncwarp();                 // warp c produced row c
        BAR_ARRIVE(0, 320);
    }

    #pragma unroll 1
    for (int l = 0; l < LAYERS; ++l) {
        const int ln  = l + 1;
        const int off = ln * DIM * DIM;

        if (g == 0) {
            // ===== A: Q = X @ Wq -> Qs =====
            Qs[r] = dot32s(Xs + c * DIM, wqp, 0.f);
            __syncwarp();
            if (l < LAYERS - 1)                     // fills wait-for-B slack
                PREFETCH_W(wqp, gWq, off, d);
            BAR_SYNC(1, 320);                       // K,V ready

            // ===== A: attention inline (per-head), Ycat -> bounce =====
            float ycat;
            {
                const int base = (d >> 3) * HD;
                u64 qv0, qv1, qv2, qv3;
                {
                    const ulonglong2* qp = (const ulonglong2*)(Qs + c * DIM + base);
                    const ulonglong2 q0 = qp[0], q1 = qp[1];
                    qv0 = q0.x; qv1 = q0.y; qv2 = q1.x; qv3 = q1.y;
                }
                float e[CTX];
                #pragma unroll
                for (int k = 0; k < CTX; ++k) {
                    if (k <= c) {
                        const ulonglong2* kp = (const ulonglong2*)(Ks + k * DIM + base);
                        const ulonglong2 k0 = kp[0], k1 = kp[1];
                        u64 acc;
                        FMUL2(acc, qv0, k0.x);
                        FFMA2(acc, qv1, k0.y);
                        FFMA2(acc, qv2, k1.x);
                        FFMA2(acc, qv3, k1.y);
                        float lo, hi; UNPK2(lo, hi, acc);
                        e[k] = __expf((lo + hi) * SCALE);
                    } else {
                        e[k] = 0.f;
                    }
                }
                const float inv =
                    __fdividef(1.f, (e[0] + e[1]) + (e[2] + e[3]) + e[4]);
                float y = e[0] * Vs[0 * DIM + d];
                y = fmaf(e[1], Vs[1 * DIM + d], y);
                y = fmaf(e[2], Vs[2 * DIM + d], y);
                y = fmaf(e[3], Vs[3 * DIM + d], y);
                y = fmaf(e[4], Vs[4 * DIM + d], y);
                ycat = y * inv;
            }
            Qs[r] = ycat;                           // intra-warp bounce
            __syncwarp();

            // ===== A: Yproj = Ycat @ Wp + bp (keep in reg AND bounce) =====
            const float yproj = dot32s(Qs + c * DIM, wpp, bpv);
            Yps[r] = yproj;
            __syncwarp();
            if (l < LAYERS - 1) {
                PREFETCH_W(wpp, gWp, off, d);
                bpv = gbp[ln * DIM + d];
            }

            // ===== A: H = relu(Yproj @ W1 + b1) =====
            const float hval = fmaxf(dot32s(Yps + c * DIM, w1p, b1v), 0.f);
            Hs[r] = hval;                           // intra-warp bounce
            __syncwarp();
            if (l < LAYERS - 1) {
                PREFETCH_W(w1p, gW1, off, d);
                b1v = gb1[ln * DIM + d];
            }

            // ===== A: Y = H @ W2 + b2 ; X += Y + Yproj =====
            const float yv = dot32s(Hs + c * DIM, w2p, b2v);
            Xs[r] += yv + yproj;                    // sole reader+writer
            __syncwarp();                           // row visible to next Q
            BAR_ARRIVE(0, 320);                     // release B
            if (l < LAYERS - 1) {
                PREFETCH_W(w2p, gW2, off, d);
                b2v = gb2[ln * DIM + d];
            }
        } else {
            // ===== B: K,V = X @ {Wk,Wv} -> Ks,Vs =====
            BAR_SYNC(0, 320);                       // X(l) ready
            Ks[r] = dot32s(Xs + c * DIM, wqp, 0.f); // wqp == Wk for B
            Vs[r] = dot32s(Xs + c * DIM, wpp, 0.f); // wpp == Wv for B
            BAR_ARRIVE(1, 320);                     // release A immediately
            if (l < LAYERS - 1) {                   // prefetch OFF crit. path
                PREFETCH_W(wqp, gWk, off, d);
                PREFETCH_W(wpp, gWv, off, d);
            } else if (r < CTX * NTOK) {            // last layer: Wu + bu
                const int t = r % NTOK;
                #pragma unroll
                for (int j = 0; j < 16; ++j) {
                    const float lo = gWu[(2 * j)     * NTOK + t];
                    const float hi = gWu[(2 * j + 1) * NTOK + t];
                    PACK2(wpp[j], lo, hi);
                }
                bpv = gbu[t];
            }
        }
    }

    // ---- Epilogue (B): wait final X, out = X @ Wu + bu ----
    if (g == 1) {
        BAR_SYNC(0, 320);
        if (r < CTX * NTOK) {
            const int cc = r / NTOK;
            out[r] = dot32s(Xs + cc * DIM, wpp, bpv);
        }
    }
}

extern "C" void kernel_launch(void* const* d_in, const int* in_sizes, int n_in,
                              void* d_out, int out_size) {
    (void)in_sizes; (void)n_in; (void)out_size;
    const int*   toks   = (const int*)  d_in[0];
    const float* pos    = (const float*)d_in[1];
    const float* tokemb = (const float*)d_in[2];
    const float* Wq     = (const float*)d_in[3];
    const float* Wk     = (const float*)d_in[4];
    const float* Wv     = (const float*)d_in[5];
    const float* Wp     = (const float*)d_in[6];
    const float* bp     = (const float*)d_in[7];
    const float* W1     = (const float*)d_in[8];
    const float* b1     = (const float*)d_in[9];
    const float* W2     = (const float*)d_in[10];
    const float* b2     = (const float*)d_in[11];
    const float* Wu     = (const float*)d_in[12];
    const float* bu     = (const float*)d_in[13];
    float* out = (float*)d_out;

    transformer_fused_kernel<<<1, 320>>>(toks, pos, tokemb, Wq, Wk, Wv, Wp, bp,
                                         W1, b1, W2, b2, Wu, bu, out);
}

// round 17
// speedup vs baseline: 1.1994x; 1.0405x over previous
#include <cuda_runtime.h>
#include <math_constants.h>

// Tiny transformer fully fused into ONE kernel, ONE block of 320 threads.
// CONTEXT=5, DIM=32, HEADS=4 (hd=8), NTOK=13, LAYERS=4.
//
// TWO warp-aligned groups of 160 threads (3 packed weight matrices each ->
// 96 weight regs, no spills):
//   A (0..159):   attention -> Yproj -> MLP -> residual.  regs: Wp+W1+W2
//   B (160..319): fused Q,K,V matmuls; final unembed.     regs: Wq+Wk+Wv->Wu
//
// SYMMETRIC barriers (robust: plain bulk-synchronous, cannot deadlock):
//   __syncthreads (layer top): X(l) ready -> B computes QKV, A prefetches.
//   bar.sync 1 (all 320):      QKV ready  -> A computes the rest,
//                              B prefetches next Wq/Wk/Wv meanwhile.
// 2 barriers per layer total (R8 had 3). All row-wise chained matmuls use
// intra-warp smem bounces (warp c owns row c). All 32-deep dots are packed
// fma.rn.f32x2 (16 FFMA2 instead of 32 FFMA). Softmax: tiny scores -> no
// max subtraction needed. tokemb staged to smem so the tok->embedding
// gather is one parallel round-trip.

#define CTX    5
#define DIM    32
#define NTOK   13
#define HEADS  4
#define HD     8
#define LAYERS 4
#define SCALE  0.17677669529663687f   // 1/sqrt(32)
#define FULL   0xFFFFFFFFu

typedef unsigned long long u64;

#define BAR_SYNC(id, n)   asm volatile("bar.sync %0, %1;" :: "n"(id), "n"(n) : "memory")

#define FFMA2(acc, a, b) asm("fma.rn.f32x2 %0, %1, %2, %0;" : "+l"(acc) : "l"(a), "l"(b))
#define FMUL2(d, a, b)   asm("mul.rn.f32x2 %0, %1, %2;" : "=l"(d) : "l"(a), "l"(b))
#define FADD2(d, a, b)   asm("add.rn.f32x2 %0, %1, %2;" : "=l"(d) : "l"(a), "l"(b))
#define PACK2(p, lo, hi) asm("mov.b64 %0, {%1, %2};" : "=l"(p) : "f"(lo), "f"(hi))
#define UNPK2(lo, hi, p) asm("mov.b64 {%0, %1}, %2;" : "=f"(lo), "=f"(hi) : "l"(p))

// 32-elem dot: loads folded in, 16 packed FMAs, depth-4 accumulators.
__device__ __forceinline__ float dot32s(const float* row, const u64* wp, float bias) {
    const ulonglong2* p = (const ulonglong2*)row;
    u64 a0, a1, a2, a3;
    PACK2(a0, bias, 0.0f);
    a1 = 0ull; a2 = 0ull; a3 = 0ull;
    #pragma unroll
    for (int i = 0; i < 4; ++i) {
        const ulonglong2 t0 = p[2 * i];
        const ulonglong2 t1 = p[2 * i + 1];
        FFMA2(a0, t0.x, wp[4 * i    ]);
        FFMA2(a1, t0.y, wp[4 * i + 1]);
        FFMA2(a2, t1.x, wp[4 * i + 2]);
        FFMA2(a3, t1.y, wp[4 * i + 3]);
    }
    u64 s0, s1;
    FADD2(s0, a0, a1);
    FADD2(s1, a2, a3);
    FADD2(s0, s0, s1);
    float lo, hi; UNPK2(lo, hi, s0);
    return lo + hi;
}

// Pack one weight column (lane d) of a [DIM,DIM] matrix into 16 u64 pairs.
#define PREFETCH_W(wp, gW, off, d) do {                                \
    _Pragma("unroll")                                                  \
    for (int _j = 0; _j < 16; ++_j) {                                  \
        const float _lo = (gW)[(off) + (2 * _j)     * DIM + (d)];      \
        const float _hi = (gW)[(off) + (2 * _j + 1) * DIM + (d)];      \
        PACK2((wp)[_j], _lo, _hi);                                     \
    } } while (0)

__global__ __launch_bounds__(320, 1)
void transformer_fused_kernel(
    const int*   __restrict__ toks,
    const float* __restrict__ pos,
    const float* __restrict__ tokemb,
    const float* __restrict__ gWq,
    const float* __restrict__ gWk,
    const float* __restrict__ gWv,
    const float* __restrict__ gWp,
    const float* __restrict__ gbp,
    const float* __restrict__ gW1,
    const float* __restrict__ gb1,
    const float* __restrict__ gW2,
    const float* __restrict__ gb2,
    const float* __restrict__ gWu,
    const float* __restrict__ gbu,
    float*       __restrict__ out)
{
    __shared__ __align__(16) float Xs  [CTX * DIM];
    __shared__ __align__(16) float Qs  [CTX * DIM];   // Q, then Ycat bounce
    __shared__ __align__(16) float Ks  [CTX * DIM];
    __shared__ __align__(16) float Vs  [CTX * DIM];
    __shared__ __align__(16) float Yps [CTX * DIM];   // Yproj bounce
    __shared__ __align__(16) float Hs  [CTX * DIM];   // H bounce
    __shared__ __align__(16) float temb[NTOK * DIM];
    __shared__ int toks_s[CTX];

    const int tid = threadIdx.x;
    const int g   = tid / 160;        // 0=A, 1=B (warp-aligned)
    const int r   = tid - g * 160;    // 0..159
    const int c   = r >> 5;           // context row (warp-uniform)
    const int d   = r & 31;           // feature column (lane)

    // Packed weight columns, 3 matrices per group (96 regs -> no spill):
    u64 wa[16], wb[16], wc[16];       // A: Wp,W1,W2   B: Wq,Wk,Wv (wc->Wu)
    float bpv = 0.f, b1v = 0.f, b2v = 0.f;   // A biases; B: bpv = bu(end)

    // ---- Prologue: stage toks/temb (A), prefetch layer-0 weights ----
    if (tid < CTX) toks_s[tid] = toks[tid];
    float posv = 0.f;
    if (g == 0) {
        posv = pos[r];
        if (r < (NTOK * DIM / 4))     // 104 float4: whole embedding table
            ((float4*)temb)[r] = ((const float4*)tokemb)[r];
        PREFETCH_W(wa, gWp, 0, d);
        PREFETCH_W(wb, gW1, 0, d);
        PREFETCH_W(wc, gW2, 0, d);
        bpv = gbp[d];
        b1v = gb1[d];
        b2v = gb2[d];
    } else {
        PREFETCH_W(wa, gWq, 0, d);
        PREFETCH_W(wb, gWk, 0, d);
        PREFETCH_W(wc, gWv, 0, d);
    }
    __syncthreads();                  // toks_s + temb visible

    // ---- Embedding (A); then full sync so B sees X(0) ----
    if (g == 0)
        Xs[r] = temb[toks_s[c] * DIM + d] + posv;
    __syncthreads();

    #pragma unroll 1
    for (int l = 0; l < LAYERS; ++l) {
        const int ln  = l + 1;
        const int off = ln * DIM * DIM;

        if (g == 1) {
            // ===== B: Q,K,V = X @ {Wq,Wk,Wv} (one LDS pass, 3 dots) =====
            const ulonglong2* p = (const ulonglong2*)(Xs + c * DIM);
            u64 q0, q1, k0, k1, v0, v1;
            q0 = q1 = k0 = k1 = v0 = v1 = 0ull;
            #pragma unroll
            for (int i = 0; i < 4; ++i) {
                const ulonglong2 t0 = p[2 * i];
                const ulonglong2 t1 = p[2 * i + 1];
                FFMA2(q0, t0.x, wa[4 * i    ]);
                FFMA2(q1, t0.y, wa[4 * i + 1]);
                FFMA2(k0, t0.x, wb[4 * i    ]);
                FFMA2(k1, t0.y, wb[4 * i + 1]);
                FFMA2(v0, t0.x, wc[4 * i    ]);
                FFMA2(v1, t0.y, wc[4 * i + 1]);
                FFMA2(q0, t1.x, wa[4 * i + 2]);
                FFMA2(q1, t1.y, wa[4 * i + 3]);
                FFMA2(k0, t1.x, wb[4 * i + 2]);
                FFMA2(k1, t1.y, wb[4 * i + 3]);
                FFMA2(v0, t1.x, wc[4 * i + 2]);
                FFMA2(v1, t1.y, wc[4 * i + 3]);
            }
            u64 s;
            float lo, hi;
            FADD2(s, q0, q1); UNPK2(lo, hi, s); Qs[r] = lo + hi;
            FADD2(s, k0, k1); UNPK2(lo, hi, s); Ks[r] = lo + hi;
            FADD2(s, v0, v1); UNPK2(lo, hi, s); Vs[r] = lo + hi;
        }
        // A overlaps B's QKV with its own next-layer prefetch (l>0 layers
        // prefetch below; nothing to do at l=0 since weights are loaded).
        BAR_SYNC(1, 320);                           // QKV ready

        if (g == 0) {
            // ===== A: attention inline (per-head), Ycat -> bounce =====
            float ycat;
            {
                const int base = (d >> 3) * HD;
                u64 qv0, qv1, qv2, qv3;
                {
                    const ulonglong2* qp = (const ulonglong2*)(Qs + c * DIM + base);
                    const ulonglong2 q0 = qp[0], q1 = qp[1];
                    qv0 = q0.x; qv1 = q0.y; qv2 = q1.x; qv3 = q1.y;
                }
                float e[CTX];
                #pragma unroll
                for (int k = 0; k < CTX; ++k) {
                    if (k <= c) {
                        const ulonglong2* kp = (const ulonglong2*)(Ks + k * DIM + base);
                        const ulonglong2 k0 = kp[0], k1 = kp[1];
                        u64 acc;
                        FMUL2(acc, qv0, k0.x);
                        FFMA2(acc, qv1, k0.y);
                        FFMA2(acc, qv2, k1.x);
                        FFMA2(acc, qv3, k1.y);
                        float lo, hi; UNPK2(lo, hi, acc);
                        e[k] = __expf((lo + hi) * SCALE);
                    } else {
                        e[k] = 0.f;
                    }
                }
                const float inv =
                    __fdividef(1.f, (e[0] + e[1]) + (e[2] + e[3]) + e[4]);
                float y = e[0] * Vs[0 * DIM + d];
                y = fmaf(e[1], Vs[1 * DIM + d], y);
                y = fmaf(e[2], Vs[2 * DIM + d], y);
                y = fmaf(e[3], Vs[3 * DIM + d], y);
                y = fmaf(e[4], Vs[4 * DIM + d], y);
                ycat = y * inv;
            }
            Qs[r] = ycat;                           // intra-warp bounce
            __syncwarp();

            // ===== A: Yproj = Ycat @ Wp + bp =====
            const float yproj = dot32s(Qs + c * DIM, wa, bpv);
            Yps[r] = yproj;
            __syncwarp();

            // ===== A: H = relu(Yproj @ W1 + b1) =====
            const float hval = fmaxf(dot32s(Yps + c * DIM, wb, b1v), 0.f);
            Hs[r] = hval;                           // intra-warp bounce
            __syncwarp();

            // ===== A: Y = H @ W2 + b2 ; X += Y + Yproj =====
            const float yv = dot32s(Hs + c * DIM, wc, b2v);
            Xs[r] += yv + yproj;                    // sole reader+writer
            if (l < LAYERS - 1) {                   // prefetch next Wp/W1/W2
                PREFETCH_W(wa, gWp, off, d);        // (overlaps B's wait)
                PREFETCH_W(wb, gW1, off, d);
                PREFETCH_W(wc, gW2, off, d);
                bpv = gbp[ln * DIM + d];
                b1v = gb1[ln * DIM + d];
                b2v = gb2[ln * DIM + d];
            }
        } else {
            // B: prefetch next layer's Wq/Wk/Wv while A runs its chain
            if (l < LAYERS - 1) {
                PREFETCH_W(wa, gWq, off, d);
                PREFETCH_W(wb, gWk, off, d);
                PREFETCH_W(wc, gWv, off, d);
            } else if (r < CTX * NTOK) {            // last layer: Wu + bu
                const int t = r % NTOK;
                #pragma unroll
                for (int j = 0; j < 16; ++j) {
                    const float lo = gWu[(2 * j)     * NTOK + t];
                    const float hi = gWu[(2 * j + 1) * NTOK + t];
                    PACK2(wc[j], lo, hi);
                }
                bpv = gbu[t];
            }
        }
        __syncthreads();                            // X(l+1) ready
    }

    // ---- Epilogue (B, Wu in regs): out = X @ Wu + bu ----
    if (g == 1 && r < CTX * NTOK) {
        const int cc = r / NTOK;
        out[r] = dot32s(Xs + cc * DIM, wc, bpv);
    }
}

extern "C" void kernel_launch(void* const* d_in, const int* in_sizes, int n_in,
                              void* d_out, int out_size) {
    (void)in_sizes; (void)n_in; (void)out_size;
    const int*   toks   = (const int*)  d_in[0];
    const float* pos    = (const float*)d_in[1];
    const float* tokemb = (const float*)d_in[2];
    const float* Wq     = (const float*)d_in[3];
    const float* Wk     = (const float*)d_in[4];
    const float* Wv     = (const float*)d_in[5];
    const float* Wp     = (const float*)d_in[6];
    const float* bp     = (const float*)d_in[7];
    const float* W1     = (const float*)d_in[8];
    const float* b1     = (const float*)d_in[9];
    const float* W2     = (const float*)d_in[10];
    const float* b2     = (const float*)d_in[11];
    const float* Wu     = (const float*)d_in[12];
    const float* bu     = (const float*)d_in[13];
    float* out = (float*)d_out;

    transformer_fused_kernel<<<1, 320>>>(toks, pos, tokemb, Wq, Wk, Wv, Wp, bp,
                                         W1, b1, W2, b2, Wu, bu, out);
}